// round 1
// baseline (speedup 1.0000x reference)
#include <cuda_runtime.h>
#include <cuda_bf16.h>
#include <math.h>

// ---------------------------------------------------------------------------
// Problem constants
// ---------------------------------------------------------------------------
#define B_     4
#define N_     8192
#define DIM_   256
#define H_     8
#define HD_    32
#define INTERNAL_ 256          // H_*HD_
#define BNTOT  (B_*N_)         // 32768
#define SCALE_ 0.17677669529663687f   // 32^-0.5

// ---------------------------------------------------------------------------
// Scratch (device globals: no allocations allowed)
// ---------------------------------------------------------------------------
__device__ float g_q[(size_t)BNTOT * INTERNAL_];   // elu(q)+1
__device__ float g_k[(size_t)BNTOT * INTERNAL_];   // elu(k)+1
__device__ float g_v[(size_t)BNTOT * INTERNAL_];
__device__ float g_o[(size_t)BNTOT * INTERNAL_];
__device__ float g_t[(size_t)BNTOT * INTERNAL_];   // pre-projection
__device__ float g_kv[B_*H_*HD_*HD_];              // kv_state (scaled by s^2)
__device__ float g_ksum[B_*H_*HD_];
__device__ float g_vsum[B_*H_*HD_];

// ---------------------------------------------------------------------------
// K0: zero the accumulators
// ---------------------------------------------------------------------------
__global__ void zero_stats_kernel() {
    int i = blockIdx.x * blockDim.x + threadIdx.x;
    const int NKV = B_*H_*HD_*HD_;
    const int NS  = B_*H_*HD_;
    if (i < NKV)     g_kv[i]   = 0.f;
    if (i < NS)      { g_ksum[i] = 0.f; g_vsum[i] = 0.f; }
}

__device__ __forceinline__ float elu1(float x) {
    return x > 0.f ? x + 1.f : __expf(x);
}

// ---------------------------------------------------------------------------
// K1: SGEMM  qkvo = x @ W_qkvo^T + b ; splits into q,k,v,o; elu+1 on q,k
//     M=32768, Nout=1024, K=256.  BM=128 BN=64 BK=16, 256 thr, 8x4/thread
// ---------------------------------------------------------------------------
#define BM 128
#define BN 64
#define BK 16

__global__ __launch_bounds__(256) void sgemm_qkvo_kernel(
    const float* __restrict__ X, const float* __restrict__ W,
    const float* __restrict__ bias)
{
    __shared__ float As[BK][BM];
    __shared__ float Bs[BK][BN];

    const int tid = threadIdx.x;
    const int tx = tid & 15;        // 0..15 -> 4 output cols
    const int ty = tid >> 4;        // 0..15 -> 8 output rows
    const int m0 = blockIdx.y * BM;
    const int j0 = blockIdx.x * BN;

    const int lr = tid >> 2;        // 0..63
    const int lc = (tid & 3) * 4;   // 0,4,8,12

    float acc[8][4];
#pragma unroll
    for (int i = 0; i < 8; i++)
#pragma unroll
        for (int j = 0; j < 4; j++) acc[i][j] = 0.f;

    for (int k0 = 0; k0 < 256; k0 += BK) {
        float4 a0 = *(const float4*)&X[(size_t)(m0 + lr)      * 256 + k0 + lc];
        float4 a1 = *(const float4*)&X[(size_t)(m0 + lr + 64) * 256 + k0 + lc];
        float4 b0 = *(const float4*)&W[(size_t)(j0 + lr)      * 256 + k0 + lc];
        __syncthreads();
        As[lc+0][lr] = a0.x; As[lc+1][lr] = a0.y; As[lc+2][lr] = a0.z; As[lc+3][lr] = a0.w;
        As[lc+0][lr+64] = a1.x; As[lc+1][lr+64] = a1.y; As[lc+2][lr+64] = a1.z; As[lc+3][lr+64] = a1.w;
        Bs[lc+0][lr] = b0.x; Bs[lc+1][lr] = b0.y; Bs[lc+2][lr] = b0.z; Bs[lc+3][lr] = b0.w;
        __syncthreads();
#pragma unroll
        for (int k = 0; k < BK; k++) {
            float4 av0 = *(const float4*)&As[k][ty*8];
            float4 av1 = *(const float4*)&As[k][ty*8+4];
            float4 bv  = *(const float4*)&Bs[k][tx*4];
            float a[8] = {av0.x,av0.y,av0.z,av0.w,av1.x,av1.y,av1.z,av1.w};
            float bb[4] = {bv.x,bv.y,bv.z,bv.w};
#pragma unroll
            for (int i = 0; i < 8; i++)
#pragma unroll
                for (int j = 0; j < 4; j++) acc[i][j] += a[i] * bb[j];
        }
    }

    const int sel = j0 >> 8;             // 0:q 1:k 2:v 3:o (BN=64 keeps block in one sel)
    float* outp = (sel == 0) ? g_q : (sel == 1) ? g_k : (sel == 2) ? g_v : g_o;
    const int colbase = (j0 & 255) + tx * 4;

#pragma unroll
    for (int i = 0; i < 8; i++) {
        int m = m0 + ty*8 + i;
        float4 v;
        v.x = acc[i][0] + bias[j0 + tx*4 + 0];
        v.y = acc[i][1] + bias[j0 + tx*4 + 1];
        v.z = acc[i][2] + bias[j0 + tx*4 + 2];
        v.w = acc[i][3] + bias[j0 + tx*4 + 3];
        if (sel <= 1) { v.x = elu1(v.x); v.y = elu1(v.y); v.z = elu1(v.z); v.w = elu1(v.w); }
        *(float4*)&outp[(size_t)m * 256 + colbase] = v;
    }
}

// ---------------------------------------------------------------------------
// K2: per-(b,h) stats: kv_state (with theta-shifted k), ksum, vsum
//     grid (B*H, NCHUNK), 1024 threads; atomicAdd partials
// ---------------------------------------------------------------------------
#define NCHUNK 16
#define CHROWS (N_ / NCHUNK)   // 512

__global__ __launch_bounds__(1024) void stats_kernel(
    const float* __restrict__ sinp, const float* __restrict__ cosp)
{
    const int bh = blockIdx.x;
    const int b  = bh >> 3;          // /H_
    const int h  = bh & 7;
    const int t  = threadIdx.x;
    const int d  = t & 31;           // kv row index (k dim)
    const int e  = t >> 5;           // kv col index (v dim) / row-slot at load

    __shared__ float ks_s[32][33];
    __shared__ float vs_s[32][33];

    const int n0 = blockIdx.y * CHROWS;
    float acc = 0.f, ksum = 0.f, vsum = 0.f;

    for (int s = 0; s < CHROWS; s += 32) {
        const int n = n0 + s + e;
        const size_t base = ((size_t)(b * N_ + n)) * INTERNAL_ + h * HD_;
        float kv0 = g_k[base + d];
        float kvn = g_k[base + (d ^ 1)];
        float vv  = g_v[base + d];
        float sn = sinp[n * HD_ + d];
        float cs = cosp[n * HD_ + d];
        float shifted = (d & 1) ? (kv0 * cs + kvn * sn) : (kv0 * cs - kvn * sn);
        __syncthreads();
        ks_s[e][d] = shifted;
        vs_s[e][d] = vv;
        ksum += kv0;
        vsum += vv;
        __syncthreads();
#pragma unroll
        for (int r = 0; r < 32; r++)
            acc += ks_s[r][d] * vs_s[r][e];
    }

    const float s2 = SCALE_ / (float)N_;
    atomicAdd(&g_kv[bh * 1024 + d * 32 + e], acc * s2);
    atomicAdd(&g_ksum[bh * 32 + d], ksum);
    atomicAdd(&g_vsum[bh * 32 + d], vsum);
}

// ---------------------------------------------------------------------------
// K3: per-token combine: z, rotary(q), attn matvec, lepe conv, *o -> g_t
//     grid B*N, 256 threads (warp == head)
// ---------------------------------------------------------------------------
__global__ __launch_bounds__(256) void token_kernel(
    const float* __restrict__ sinp, const float* __restrict__ cosp,
    const float* __restrict__ Wl,   const float* __restrict__ bl)
{
    const int bidx = blockIdx.x;          // b*N + n
    const int n = bidx & (N_ - 1);
    const int b = bidx >> 13;             // /N_ (8192)
    const int t = threadIdx.x;
    const int lane = t & 31;
    const int h = t >> 5;
    const int c = h * HD_ + lane;
    const size_t base = (size_t)bidx * INTERNAL_;
    const int bh = b * H_ + h;

    const float invN = 1.0f / (float)N_;
    float q = g_q[base + c];

    // z = SCALE * dot(q_head, kmean)
    float zp = q * (g_ksum[bh * 32 + lane] * invN);
#pragma unroll
    for (int o = 16; o; o >>= 1) zp += __shfl_xor_sync(0xffffffffu, zp, o);
    float z = zp * SCALE_;

    // theta shift q
    float qn = __shfl_xor_sync(0xffffffffu, q, 1);
    float sn = sinp[n * HD_ + lane];
    float cs = cosp[n * HD_ + lane];
    float qs = (lane & 1) ? (q * cs + qn * sn) : (q * cs - qn * sn);

    // attn = qs @ kv_state  (32x32, state already has s^2)
    const float* kvp = &g_kv[bh * 1024];
    float attn = 0.f;
#pragma unroll
    for (int d2 = 0; d2 < 32; d2++) {
        float qd = __shfl_sync(0xffffffffu, qs, d2);
        attn += qd * kvp[d2 * 32 + lane];
    }

    float vm = g_vsum[bh * 32 + lane] * invN;
    float res = attn * (1.0f + 1.0f / (z + 1e-6f)) - z * vm;

    // lepe depthwise conv (padding 1, per batch)
    float w0 = Wl[c * 3 + 0], w1 = Wl[c * 3 + 1], w2 = Wl[c * 3 + 2];
    float vprev = (n > 0)       ? g_v[base - 256 + c] : 0.f;
    float vcur  = g_v[base + c];
    float vnext = (n < N_ - 1)  ? g_v[base + 256 + c] : 0.f;
    float lepe = vprev * w0 + vcur * w1 + vnext * w2 + bl[c];

    g_t[base + c] = (res + lepe) * g_o[base + c];
}

// ---------------------------------------------------------------------------
// K4: SGEMM  out = t @ W_proj^T + b_proj ; M=32768, Nout=256, K=256
// ---------------------------------------------------------------------------
__global__ __launch_bounds__(256) void sgemm_proj_kernel(
    const float* __restrict__ W, const float* __restrict__ bias,
    float* __restrict__ out)
{
    __shared__ float As[BK][BM];
    __shared__ float Bs[BK][BN];

    const int tid = threadIdx.x;
    const int tx = tid & 15;
    const int ty = tid >> 4;
    const int m0 = blockIdx.y * BM;
    const int j0 = blockIdx.x * BN;

    const int lr = tid >> 2;
    const int lc = (tid & 3) * 4;

    float acc[8][4];
#pragma unroll
    for (int i = 0; i < 8; i++)
#pragma unroll
        for (int j = 0; j < 4; j++) acc[i][j] = 0.f;

    for (int k0 = 0; k0 < 256; k0 += BK) {
        float4 a0 = *(const float4*)&g_t[(size_t)(m0 + lr)      * 256 + k0 + lc];
        float4 a1 = *(const float4*)&g_t[(size_t)(m0 + lr + 64) * 256 + k0 + lc];
        float4 b0 = *(const float4*)&W[(size_t)(j0 + lr)        * 256 + k0 + lc];
        __syncthreads();
        As[lc+0][lr] = a0.x; As[lc+1][lr] = a0.y; As[lc+2][lr] = a0.z; As[lc+3][lr] = a0.w;
        As[lc+0][lr+64] = a1.x; As[lc+1][lr+64] = a1.y; As[lc+2][lr+64] = a1.z; As[lc+3][lr+64] = a1.w;
        Bs[lc+0][lr] = b0.x; Bs[lc+1][lr] = b0.y; Bs[lc+2][lr] = b0.z; Bs[lc+3][lr] = b0.w;
        __syncthreads();
#pragma unroll
        for (int k = 0; k < BK; k++) {
            float4 av0 = *(const float4*)&As[k][ty*8];
            float4 av1 = *(const float4*)&As[k][ty*8+4];
            float4 bv  = *(const float4*)&Bs[k][tx*4];
            float a[8] = {av0.x,av0.y,av0.z,av0.w,av1.x,av1.y,av1.z,av1.w};
            float bb[4] = {bv.x,bv.y,bv.z,bv.w};
#pragma unroll
            for (int i = 0; i < 8; i++)
#pragma unroll
                for (int j = 0; j < 4; j++) acc[i][j] += a[i] * bb[j];
        }
    }

#pragma unroll
    for (int i = 0; i < 8; i++) {
        int m = m0 + ty*8 + i;
        float4 v;
        v.x = acc[i][0] + bias[j0 + tx*4 + 0];
        v.y = acc[i][1] + bias[j0 + tx*4 + 1];
        v.z = acc[i][2] + bias[j0 + tx*4 + 2];
        v.w = acc[i][3] + bias[j0 + tx*4 + 3];
        *(float4*)&out[(size_t)m * 256 + j0 + tx*4] = v;
    }
}

// ---------------------------------------------------------------------------
// Launch
// inputs: 0=x 1=sin 2=cos 3=W_qkvo 4=b_qkvo 5=W_lepe 6=b_lepe 7=W_proj 8=b_proj
// ---------------------------------------------------------------------------
extern "C" void kernel_launch(void* const* d_in, const int* in_sizes, int n_in,
                              void* d_out, int out_size)
{
    const float* x      = (const float*)d_in[0];
    const float* sinp   = (const float*)d_in[1];
    const float* cosp   = (const float*)d_in[2];
    const float* W_qkvo = (const float*)d_in[3];
    const float* b_qkvo = (const float*)d_in[4];
    const float* W_lepe = (const float*)d_in[5];
    const float* b_lepe = (const float*)d_in[6];
    const float* W_proj = (const float*)d_in[7];
    const float* b_proj = (const float*)d_in[8];
    float* out = (float*)d_out;

    // K0: zero stats
    zero_stats_kernel<<<(B_*H_*HD_*HD_ + 255) / 256, 256>>>();

    // K1: qkvo GEMM + split + elu
    dim3 g1(1024 / BN, BNTOT / BM);
    sgemm_qkvo_kernel<<<g1, 256>>>(x, W_qkvo, b_qkvo);

    // K2: kv_state / ksum / vsum
    dim3 g2(B_ * H_, NCHUNK);
    stats_kernel<<<g2, 1024>>>(sinp, cosp);

    // K3: per-token combine
    token_kernel<<<BNTOT, 256>>>(sinp, cosp, W_lepe, b_lepe);

    // K4: projection GEMM
    dim3 g4(256 / BN, BNTOT / BM);
    sgemm_proj_kernel<<<g4, 256>>>(W_proj, b_proj, out);
}

// round 2
// speedup vs baseline: 1.4566x; 1.4566x over previous
#include <cuda_runtime.h>
#include <cuda_bf16.h>
#include <math.h>
#include <stdint.h>

// ---------------------------------------------------------------------------
// Problem constants
// ---------------------------------------------------------------------------
#define B_     4
#define N_     8192
#define DIM_   256
#define H_     8
#define HD_    32
#define INTERNAL_ 256          // H_*HD_
#define BNTOT  (B_*N_)         // 32768
#define SCALE_ 0.17677669529663687f   // 32^-0.5

// ---------------------------------------------------------------------------
// Scratch (device globals: no allocations allowed)
// ---------------------------------------------------------------------------
__device__ float g_q[(size_t)BNTOT * INTERNAL_];   // elu(q)+1
__device__ float g_k[(size_t)BNTOT * INTERNAL_];   // elu(k)+1
__device__ float g_v[(size_t)BNTOT * INTERNAL_];
__device__ float g_o[(size_t)BNTOT * INTERNAL_];
__device__ float g_kv[B_*H_*HD_*HD_];              // kv_state (scaled by s^2)
__device__ float g_ksum[B_*H_*HD_];
__device__ float g_vsum[B_*H_*HD_];

// bf16 split operands
__device__ __nv_bfloat16 g_xh[(size_t)BNTOT * DIM_];
__device__ __nv_bfloat16 g_xl[(size_t)BNTOT * DIM_];
__device__ __nv_bfloat16 g_wqh[4 * INTERNAL_ * DIM_];
__device__ __nv_bfloat16 g_wql[4 * INTERNAL_ * DIM_];
__device__ __nv_bfloat16 g_wph[DIM_ * INTERNAL_];
__device__ __nv_bfloat16 g_wpl[DIM_ * INTERNAL_];
__device__ __nv_bfloat16 g_th[(size_t)BNTOT * INTERNAL_];
__device__ __nv_bfloat16 g_tl[(size_t)BNTOT * INTERNAL_];

// ---------------------------------------------------------------------------
// K0: zero the accumulators
// ---------------------------------------------------------------------------
__global__ void zero_stats_kernel() {
    int i = blockIdx.x * blockDim.x + threadIdx.x;
    const int NKV = B_*H_*HD_*HD_;
    const int NS  = B_*H_*HD_;
    if (i < NKV)     g_kv[i]   = 0.f;
    if (i < NS)      { g_ksum[i] = 0.f; g_vsum[i] = 0.f; }
}

__device__ __forceinline__ float elu1(float x) {
    return x > 0.f ? x + 1.f : __expf(x);
}

// ---------------------------------------------------------------------------
// split fp32 -> bf16 hi + bf16 lo
// ---------------------------------------------------------------------------
__global__ void split_kernel(const float* __restrict__ src,
                             __nv_bfloat16* __restrict__ hi,
                             __nv_bfloat16* __restrict__ lo, int n)
{
    int i = blockIdx.x * blockDim.x + threadIdx.x;
    if (i * 4 < n) {
        float4 v = *(const float4*)&src[i * 4];
        __nv_bfloat16 h0 = __float2bfloat16(v.x);
        __nv_bfloat16 h1 = __float2bfloat16(v.y);
        __nv_bfloat16 h2 = __float2bfloat16(v.z);
        __nv_bfloat16 h3 = __float2bfloat16(v.w);
        __nv_bfloat162* hp = (__nv_bfloat162*)&hi[i * 4];
        hp[0] = __nv_bfloat162(h0, h1);
        hp[1] = __nv_bfloat162(h2, h3);
        __nv_bfloat162* lp = (__nv_bfloat162*)&lo[i * 4];
        lp[0] = __nv_bfloat162(__float2bfloat16(v.x - __bfloat162float(h0)),
                               __float2bfloat16(v.y - __bfloat162float(h1)));
        lp[1] = __nv_bfloat162(__float2bfloat16(v.z - __bfloat162float(h2)),
                               __float2bfloat16(v.w - __bfloat162float(h3)));
    }
}

// ---------------------------------------------------------------------------
// Tensor-core split-bf16 GEMM:  C[M x Nout] = A[M x 256] @ W[Nout x 256]^T + b
// BM=128 BN=64 BK=32, 256 threads (8 warps, 4x2), warp tile 32x32.
// EPI==1: split epilogue -> g_q/g_k/g_v/g_o with elu on q,k.
// EPI==0: write to Cout (stride 256).
// ---------------------------------------------------------------------------
#define LDP 20   // row stride in u32 (=40 bf16, bank-conflict-free)

__device__ __forceinline__ void mma16816(float* c, const uint32_t* a, const uint32_t* b)
{
    asm volatile(
        "mma.sync.aligned.m16n8k16.row.col.f32.bf16.bf16.f32 "
        "{%0,%1,%2,%3},{%4,%5,%6,%7},{%8,%9},{%0,%1,%2,%3};"
        : "+f"(c[0]), "+f"(c[1]), "+f"(c[2]), "+f"(c[3])
        : "r"(a[0]), "r"(a[1]), "r"(a[2]), "r"(a[3]), "r"(b[0]), "r"(b[1]));
}

template<int EPI>
__global__ __launch_bounds__(256) void mma_gemm(
    const __nv_bfloat16* __restrict__ Ahi, const __nv_bfloat16* __restrict__ Alo,
    const __nv_bfloat16* __restrict__ Bhi, const __nv_bfloat16* __restrict__ Blo,
    const float* __restrict__ bias, float* __restrict__ Cout)
{
    __shared__ __align__(16) uint32_t sA[2][128 * LDP];
    __shared__ __align__(16) uint32_t sB[2][64 * LDP];

    const int tid  = threadIdx.x;
    const int lane = tid & 31;
    const int wid  = tid >> 5;
    const int wm   = wid & 3;          // 0..3
    const int wn   = wid >> 2;         // 0..1
    const int g    = lane >> 2;        // 0..7
    const int t    = lane & 3;         // 0..3

    const int m0 = blockIdx.y * 128;
    const int j0 = blockIdx.x * 64;

    // A: 2 chunks/thread, B: 1 chunk/thread; chunk = 16B (8 bf16)
    const int ar0 = tid >> 2,        ac0 = tid & 3;          // chunk tid
    const int ar1 = (tid + 256) >> 2, ac1 = tid & 3;          // chunk tid+256
    const int br  = tid >> 2,        bc  = tid & 3;          // 0..63 rows

    uint4 paH[2], paL[2], pbH, pbL;

    auto loadg = [&](int kt) {
        size_t a0off = (size_t)(m0 + ar0) * 256 + kt * 32 + ac0 * 8;
        size_t a1off = (size_t)(m0 + ar1) * 256 + kt * 32 + ac1 * 8;
        size_t boff  = (size_t)(j0 + br)  * 256 + kt * 32 + bc * 8;
        paH[0] = *(const uint4*)&Ahi[a0off];
        paH[1] = *(const uint4*)&Ahi[a1off];
        paL[0] = *(const uint4*)&Alo[a0off];
        paL[1] = *(const uint4*)&Alo[a1off];
        pbH    = *(const uint4*)&Bhi[boff];
        pbL    = *(const uint4*)&Blo[boff];
    };

    float acc[2][4][4];
#pragma unroll
    for (int i = 0; i < 2; i++)
#pragma unroll
        for (int j = 0; j < 4; j++)
#pragma unroll
            for (int r = 0; r < 4; r++) acc[i][j][r] = 0.f;

    loadg(0);

    for (int kt = 0; kt < 8; kt++) {
        __syncthreads();
        *(uint4*)&sA[0][ar0 * LDP + ac0 * 4] = paH[0];
        *(uint4*)&sA[0][ar1 * LDP + ac1 * 4] = paH[1];
        *(uint4*)&sA[1][ar0 * LDP + ac0 * 4] = paL[0];
        *(uint4*)&sA[1][ar1 * LDP + ac1 * 4] = paL[1];
        *(uint4*)&sB[0][br * LDP + bc * 4]   = pbH;
        *(uint4*)&sB[1][br * LDP + bc * 4]   = pbL;
        __syncthreads();
        if (kt < 7) loadg(kt + 1);

#pragma unroll
        for (int kp = 0; kp < 16; kp += 8) {
            uint32_t aH[2][4], aL[2][4], bH[4][2], bL[4][2];
#pragma unroll
            for (int i = 0; i < 2; i++) {
                int r = wm * 32 + i * 16 + g;
                aH[i][0] = sA[0][r * LDP + kp + t];
                aH[i][1] = sA[0][(r + 8) * LDP + kp + t];
                aH[i][2] = sA[0][r * LDP + kp + t + 4];
                aH[i][3] = sA[0][(r + 8) * LDP + kp + t + 4];
                aL[i][0] = sA[1][r * LDP + kp + t];
                aL[i][1] = sA[1][(r + 8) * LDP + kp + t];
                aL[i][2] = sA[1][r * LDP + kp + t + 4];
                aL[i][3] = sA[1][(r + 8) * LDP + kp + t + 4];
            }
#pragma unroll
            for (int j = 0; j < 4; j++) {
                int r = wn * 32 + j * 8 + g;
                bH[j][0] = sB[0][r * LDP + kp + t];
                bH[j][1] = sB[0][r * LDP + kp + t + 4];
                bL[j][0] = sB[1][r * LDP + kp + t];
                bL[j][1] = sB[1][r * LDP + kp + t + 4];
            }
#pragma unroll
            for (int i = 0; i < 2; i++)
#pragma unroll
                for (int j = 0; j < 4; j++) {
                    mma16816(acc[i][j], aH[i], bH[j]);
                    mma16816(acc[i][j], aH[i], bL[j]);
                    mma16816(acc[i][j], aL[i], bH[j]);
                }
        }
    }

    // epilogue
    float* outp = Cout;
    int sel = 0;
    if (EPI == 1) {
        sel = j0 >> 8;
        outp = (sel == 0) ? g_q : (sel == 1) ? g_k : (sel == 2) ? g_v : g_o;
    }

#pragma unroll
    for (int i = 0; i < 2; i++) {
#pragma unroll
        for (int j = 0; j < 4; j++) {
            int jc = j0 + wn * 32 + j * 8 + 2 * t;
            float bx = bias[jc], by = bias[jc + 1];
            int m = m0 + wm * 32 + i * 16 + g;
            float2 v0 = make_float2(acc[i][j][0] + bx, acc[i][j][1] + by);
            float2 v1 = make_float2(acc[i][j][2] + bx, acc[i][j][3] + by);
            if (EPI == 1 && sel <= 1) {
                v0.x = elu1(v0.x); v0.y = elu1(v0.y);
                v1.x = elu1(v1.x); v1.y = elu1(v1.y);
            }
            int col = (EPI == 1) ? (jc & 255) : jc;
            *(float2*)&outp[(size_t)m * 256 + col]       = v0;
            *(float2*)&outp[(size_t)(m + 8) * 256 + col] = v1;
        }
    }
}

// ---------------------------------------------------------------------------
// K2: per-(b,h) stats: kv_state (with theta-shifted k), ksum, vsum
// ---------------------------------------------------------------------------
#define NCHUNK 16
#define CHROWS (N_ / NCHUNK)   // 512

__global__ __launch_bounds__(1024) void stats_kernel(
    const float* __restrict__ sinp, const float* __restrict__ cosp)
{
    const int bh = blockIdx.x;
    const int b  = bh >> 3;
    const int h  = bh & 7;
    const int t  = threadIdx.x;
    const int d  = t & 31;
    const int e  = t >> 5;

    __shared__ float ks_s[32][33];
    __shared__ float vs_s[32][33];

    const int n0 = blockIdx.y * CHROWS;
    float acc = 0.f, ksum = 0.f, vsum = 0.f;

    for (int s = 0; s < CHROWS; s += 32) {
        const int n = n0 + s + e;
        const size_t base = ((size_t)(b * N_ + n)) * INTERNAL_ + h * HD_;
        float kv0 = g_k[base + d];
        float kvn = g_k[base + (d ^ 1)];
        float vv  = g_v[base + d];
        float sn = sinp[n * HD_ + d];
        float cs = cosp[n * HD_ + d];
        float shifted = (d & 1) ? (kv0 * cs + kvn * sn) : (kv0 * cs - kvn * sn);
        __syncthreads();
        ks_s[e][d] = shifted;
        vs_s[e][d] = vv;
        ksum += kv0;
        vsum += vv;
        __syncthreads();
#pragma unroll
        for (int r = 0; r < 32; r++)
            acc += ks_s[r][d] * vs_s[r][e];
    }

    const float s2 = SCALE_ / (float)N_;
    atomicAdd(&g_kv[bh * 1024 + d * 32 + e], acc * s2);
    atomicAdd(&g_ksum[bh * 32 + d], ksum);
    atomicAdd(&g_vsum[bh * 32 + d], vsum);
}

// ---------------------------------------------------------------------------
// K3: per-token combine -> t (written as bf16 hi/lo pair for GEMM2)
// ---------------------------------------------------------------------------
__global__ __launch_bounds__(256) void token_kernel(
    const float* __restrict__ sinp, const float* __restrict__ cosp,
    const float* __restrict__ Wl,   const float* __restrict__ bl)
{
    const int bidx = blockIdx.x;          // b*N + n
    const int n = bidx & (N_ - 1);
    const int b = bidx >> 13;
    const int t = threadIdx.x;
    const int lane = t & 31;
    const int h = t >> 5;
    const int c = h * HD_ + lane;
    const size_t base = (size_t)bidx * INTERNAL_;
    const int bh = b * H_ + h;

    const float invN = 1.0f / (float)N_;
    float q = g_q[base + c];

    // z = SCALE * dot(q_head, kmean)
    float zp = q * (g_ksum[bh * 32 + lane] * invN);
#pragma unroll
    for (int o = 16; o; o >>= 1) zp += __shfl_xor_sync(0xffffffffu, zp, o);
    float z = zp * SCALE_;

    // theta shift q
    float qn = __shfl_xor_sync(0xffffffffu, q, 1);
    float sn = sinp[n * HD_ + lane];
    float cs = cosp[n * HD_ + lane];
    float qs = (lane & 1) ? (q * cs + qn * sn) : (q * cs - qn * sn);

    // attn = qs @ kv_state  (32x32, state already has s^2)
    const float* kvp = &g_kv[bh * 1024];
    float attn = 0.f;
#pragma unroll
    for (int d2 = 0; d2 < 32; d2++) {
        float qd = __shfl_sync(0xffffffffu, qs, d2);
        attn += qd * kvp[d2 * 32 + lane];
    }

    float vm = g_vsum[bh * 32 + lane] * invN;
    float res = attn * (1.0f + 1.0f / (z + 1e-6f)) - z * vm;

    // lepe depthwise conv (padding 1, per batch)
    float w0 = Wl[c * 3 + 0], w1 = Wl[c * 3 + 1], w2 = Wl[c * 3 + 2];
    float vprev = (n > 0)       ? g_v[base - 256 + c] : 0.f;
    float vcur  = g_v[base + c];
    float vnext = (n < N_ - 1)  ? g_v[base + 256 + c] : 0.f;
    float lepe = vprev * w0 + vcur * w1 + vnext * w2 + bl[c];

    float tv = (res + lepe) * g_o[base + c];
    __nv_bfloat16 hv = __float2bfloat16(tv);
    g_th[base + c] = hv;
    g_tl[base + c] = __float2bfloat16(tv - __bfloat162float(hv));
}

// ---------------------------------------------------------------------------
// Launch
// inputs: 0=x 1=sin 2=cos 3=W_qkvo 4=b_qkvo 5=W_lepe 6=b_lepe 7=W_proj 8=b_proj
// ---------------------------------------------------------------------------
extern "C" void kernel_launch(void* const* d_in, const int* in_sizes, int n_in,
                              void* d_out, int out_size)
{
    const float* x      = (const float*)d_in[0];
    const float* sinp   = (const float*)d_in[1];
    const float* cosp   = (const float*)d_in[2];
    const float* W_qkvo = (const float*)d_in[3];
    const float* b_qkvo = (const float*)d_in[4];
    const float* W_lepe = (const float*)d_in[5];
    const float* b_lepe = (const float*)d_in[6];
    const float* W_proj = (const float*)d_in[7];
    const float* b_proj = (const float*)d_in[8];
    float* out = (float*)d_out;

    __nv_bfloat16 *xh, *xl, *wqh, *wql, *wph, *wpl, *th, *tl;
    cudaGetSymbolAddress((void**)&xh,  g_xh);
    cudaGetSymbolAddress((void**)&xl,  g_xl);
    cudaGetSymbolAddress((void**)&wqh, g_wqh);
    cudaGetSymbolAddress((void**)&wql, g_wql);
    cudaGetSymbolAddress((void**)&wph, g_wph);
    cudaGetSymbolAddress((void**)&wpl, g_wpl);
    cudaGetSymbolAddress((void**)&th,  g_th);
    cudaGetSymbolAddress((void**)&tl,  g_tl);

    // K0: zero stats
    zero_stats_kernel<<<(B_*H_*HD_*HD_ + 255) / 256, 256>>>();

    // splits
    {
        int n1 = BNTOT * DIM_;
        split_kernel<<<(n1/4 + 255)/256, 256>>>(x, xh, xl, n1);
        int n2 = 4 * INTERNAL_ * DIM_;
        split_kernel<<<(n2/4 + 255)/256, 256>>>(W_qkvo, wqh, wql, n2);
        int n3 = DIM_ * INTERNAL_;
        split_kernel<<<(n3/4 + 255)/256, 256>>>(W_proj, wph, wpl, n3);
    }

    // K1: qkvo GEMM (tensor cores) + split + elu
    mma_gemm<1><<<dim3(16, 256), 256>>>(xh, xl, wqh, wql, b_qkvo, nullptr);

    // K2: kv_state / ksum / vsum
    dim3 g2(B_ * H_, NCHUNK);
    stats_kernel<<<g2, 1024>>>(sinp, cosp);

    // K3: per-token combine
    token_kernel<<<BNTOT, 256>>>(sinp, cosp, W_lepe, b_lepe);

    // K4: projection GEMM (tensor cores)
    mma_gemm<0><<<dim3(4, 256), 256>>>(th, tl, wph, wpl, b_proj, out);
}

// round 6
// speedup vs baseline: 1.9916x; 1.3673x over previous
#include <cuda_runtime.h>
#include <cuda_bf16.h>
#include <math.h>
#include <stdint.h>

// ---------------------------------------------------------------------------
// Problem constants
// ---------------------------------------------------------------------------
#define B_     4
#define N_     8192
#define DIM_   256
#define H_     8
#define HD_    32
#define INTERNAL_ 256
#define BNTOT  (B_*N_)
#define SCALE_ 0.17677669529663687f

// ---------------------------------------------------------------------------
// Scratch
// ---------------------------------------------------------------------------
__device__ float g_q[(size_t)BNTOT * INTERNAL_];
__device__ float g_k[(size_t)BNTOT * INTERNAL_];
__device__ float g_v[(size_t)BNTOT * INTERNAL_];
__device__ float g_o[(size_t)BNTOT * INTERNAL_];
__device__ float g_kv[B_*H_*HD_*HD_];
__device__ float g_ksum[B_*H_*HD_];
__device__ float g_vsum[B_*H_*HD_];

__device__ __nv_bfloat16 g_xh[(size_t)BNTOT * DIM_];
__device__ __nv_bfloat16 g_xl[(size_t)BNTOT * DIM_];
__device__ __nv_bfloat16 g_wqh[4 * INTERNAL_ * DIM_];
__device__ __nv_bfloat16 g_wql[4 * INTERNAL_ * DIM_];
__device__ __nv_bfloat16 g_wph[DIM_ * INTERNAL_];
__device__ __nv_bfloat16 g_wpl[DIM_ * INTERNAL_];
__device__ __nv_bfloat16 g_th[(size_t)BNTOT * INTERNAL_];
__device__ __nv_bfloat16 g_tl[(size_t)BNTOT * INTERNAL_];

// ---------------------------------------------------------------------------
__global__ void zero_stats_kernel() {
    int i = blockIdx.x * blockDim.x + threadIdx.x;
    const int NKV = B_*H_*HD_*HD_;
    const int NS  = B_*H_*HD_;
    if (i < NKV)     g_kv[i]   = 0.f;
    if (i < NS)      { g_ksum[i] = 0.f; g_vsum[i] = 0.f; }
}

__device__ __forceinline__ float elu1(float x) {
    return x > 0.f ? x + 1.f : __expf(x);
}

// ---------------------------------------------------------------------------
__global__ void split_kernel(const float* __restrict__ src,
                             __nv_bfloat16* __restrict__ hi,
                             __nv_bfloat16* __restrict__ lo, int n)
{
    int i = blockIdx.x * blockDim.x + threadIdx.x;
    if (i * 4 < n) {
        float4 v = *(const float4*)&src[i * 4];
        __nv_bfloat16 h0 = __float2bfloat16(v.x);
        __nv_bfloat16 h1 = __float2bfloat16(v.y);
        __nv_bfloat16 h2 = __float2bfloat16(v.z);
        __nv_bfloat16 h3 = __float2bfloat16(v.w);
        __nv_bfloat162* hp = (__nv_bfloat162*)&hi[i * 4];
        hp[0] = __nv_bfloat162(h0, h1);
        hp[1] = __nv_bfloat162(h2, h3);
        __nv_bfloat162* lp = (__nv_bfloat162*)&lo[i * 4];
        lp[0] = __nv_bfloat162(__float2bfloat16(v.x - __bfloat162float(h0)),
                               __float2bfloat16(v.y - __bfloat162float(h1)));
        lp[1] = __nv_bfloat162(__float2bfloat16(v.z - __bfloat162float(h2)),
                               __float2bfloat16(v.w - __bfloat162float(h3)));
    }
}

// ---------------------------------------------------------------------------
// Tensor-core split-bf16 GEMM with ldmatrix + cp.async double buffering.
// C[M x Nout] = A[M x 256] @ W[Nout x 256]^T + bias
// BM=128 BN=128 BK=32; 8 warps as 2(m) x 4(n); warp tile 64 x 32.
// ---------------------------------------------------------------------------
#define LDP 20                 // row stride in u32 (40 bf16): conflict-free
#define STG_U32 10240          // 40KB per stage in u32
#define AH_OFF 0
#define AL_OFF 2560
#define BH_OFF 5120
#define BL_OFF 7680

__device__ __forceinline__ void mma16816(float* c, const uint32_t* a, const uint32_t* b)
{
    asm volatile(
        "mma.sync.aligned.m16n8k16.row.col.f32.bf16.bf16.f32 "
        "{%0,%1,%2,%3},{%4,%5,%6,%7},{%8,%9},{%0,%1,%2,%3};"
        : "+f"(c[0]), "+f"(c[1]), "+f"(c[2]), "+f"(c[3])
        : "r"(a[0]), "r"(a[1]), "r"(a[2]), "r"(a[3]), "r"(b[0]), "r"(b[1]));
}

__device__ __forceinline__ void ldsm4(uint32_t* r, uint32_t addr)
{
    asm volatile("ldmatrix.sync.aligned.m8n8.x4.shared.b16 {%0,%1,%2,%3},[%4];"
                 : "=r"(r[0]), "=r"(r[1]), "=r"(r[2]), "=r"(r[3]) : "r"(addr));
}

__device__ __forceinline__ void cpasync16(uint32_t sdst, const void* gsrc)
{
    asm volatile("cp.async.ca.shared.global [%0], [%1], 16;" :: "r"(sdst), "l"(gsrc));
}

template<int EPI>
__global__ __launch_bounds__(256) void mma_gemm(
    const __nv_bfloat16* __restrict__ Ahi, const __nv_bfloat16* __restrict__ Alo,
    const __nv_bfloat16* __restrict__ Bhi, const __nv_bfloat16* __restrict__ Blo,
    const float* __restrict__ bias, float* __restrict__ Cout)
{
    extern __shared__ __align__(16) uint32_t smem[];
    const uint32_t sbase = (uint32_t)__cvta_generic_to_shared(smem);

    const int tid  = threadIdx.x;
    const int lane = tid & 31;
    const int wid  = tid >> 5;
    const int wm   = wid & 1;
    const int wn   = wid >> 1;

    const int m0 = blockIdx.y * 128;
    const int j0 = blockIdx.x * 128;

    // cp.async source rows: thread handles chunk tid (rows 0..63) and tid+256
    const int r0 = tid >> 2,  c0 = tid & 3;
    const int r1 = r0 + 64;

    auto issue = [&](int kt, int st) {
        const uint32_t sb = sbase + (st * STG_U32) * 4;
        size_t ga0 = (size_t)(m0 + r0) * 256 + kt * 32 + c0 * 8;
        size_t ga1 = (size_t)(m0 + r1) * 256 + kt * 32 + c0 * 8;
        size_t gb0 = (size_t)(j0 + r0) * 256 + kt * 32 + c0 * 8;
        size_t gb1 = (size_t)(j0 + r1) * 256 + kt * 32 + c0 * 8;
        uint32_t d0 = (r0 * LDP + c0 * 4) * 4;
        uint32_t d1 = (r1 * LDP + c0 * 4) * 4;
        cpasync16(sb + AH_OFF*4 + d0, &Ahi[ga0]);
        cpasync16(sb + AH_OFF*4 + d1, &Ahi[ga1]);
        cpasync16(sb + AL_OFF*4 + d0, &Alo[ga0]);
        cpasync16(sb + AL_OFF*4 + d1, &Alo[ga1]);
        cpasync16(sb + BH_OFF*4 + d0, &Bhi[gb0]);
        cpasync16(sb + BH_OFF*4 + d1, &Bhi[gb1]);
        cpasync16(sb + BL_OFF*4 + d0, &Blo[gb0]);
        cpasync16(sb + BL_OFF*4 + d1, &Blo[gb1]);
    };

    // ldmatrix per-lane base offsets (u32 units)
    const uint32_t a_base = (uint32_t)((wm * 64 + (lane & 15)) * LDP + ((lane >> 4) * 4));
    const uint32_t b_base = (uint32_t)((wn * 32 + (lane & 7) + (((lane >> 4) & 1) * 8)) * LDP
                                       + (((lane >> 3) & 1) * 4));

    float acc[4][4][4];
#pragma unroll
    for (int i = 0; i < 4; i++)
#pragma unroll
        for (int j = 0; j < 4; j++)
#pragma unroll
            for (int r = 0; r < 4; r++) acc[i][j][r] = 0.f;

    issue(0, 0);
    asm volatile("cp.async.commit_group;");

    for (int kt = 0; kt < 8; kt++) {
        const int st = kt & 1;
        if (kt < 7) {
            issue(kt + 1, st ^ 1);
            asm volatile("cp.async.commit_group;");
            asm volatile("cp.async.wait_group 1;");
        } else {
            asm volatile("cp.async.wait_group 0;");
        }
        __syncthreads();

        const uint32_t sb = sbase + (st * STG_U32) * 4;
#pragma unroll
        for (int kp = 0; kp < 2; kp++) {
            uint32_t aH[4][4], aL[4][4], bH[2][4], bL[2][4];
#pragma unroll
            for (int mi = 0; mi < 4; mi++) {
                uint32_t ao = (a_base + mi * (16 * LDP) + kp * 8) * 4;
                ldsm4(aH[mi], sb + AH_OFF*4 + ao);
                ldsm4(aL[mi], sb + AL_OFF*4 + ao);
            }
#pragma unroll
            for (int nj = 0; nj < 2; nj++) {
                uint32_t bo = (b_base + nj * (16 * LDP) + kp * 8) * 4;
                ldsm4(bH[nj], sb + BH_OFF*4 + bo);
                ldsm4(bL[nj], sb + BL_OFF*4 + bo);
            }
#pragma unroll
            for (int mi = 0; mi < 4; mi++)
#pragma unroll
                for (int nt = 0; nt < 4; nt++) {
                    const uint32_t* bh = &bH[nt >> 1][(nt & 1) * 2];
                    const uint32_t* bl = &bL[nt >> 1][(nt & 1) * 2];
                    mma16816(acc[mi][nt], aH[mi], bh);
                    mma16816(acc[mi][nt], aH[mi], bl);
                    mma16816(acc[mi][nt], aL[mi], bh);
                }
        }
        __syncthreads();
    }

    // epilogue
    float* outp = Cout;
    int sel = 0;
    if (EPI == 1) {
        sel = j0 >> 8;
        outp = (sel == 0) ? g_q : (sel == 1) ? g_k : (sel == 2) ? g_v : g_o;
    }

#pragma unroll
    for (int mi = 0; mi < 4; mi++) {
#pragma unroll
        for (int nt = 0; nt < 4; nt++) {
            int jc = j0 + wn * 32 + nt * 8 + 2 * (lane & 3);
            float bx = bias[jc], by = bias[jc + 1];
            int m = m0 + wm * 64 + mi * 16 + (lane >> 2);
            float2 v0 = make_float2(acc[mi][nt][0] + bx, acc[mi][nt][1] + by);
            float2 v1 = make_float2(acc[mi][nt][2] + bx, acc[mi][nt][3] + by);
            if (EPI == 1 && sel <= 1) {
                v0.x = elu1(v0.x); v0.y = elu1(v0.y);
                v1.x = elu1(v1.x); v1.y = elu1(v1.y);
            }
            int col = (EPI == 1) ? ((j0 & 255) + wn * 32 + nt * 8 + 2 * (lane & 3)) : jc;
            *(float2*)&outp[(size_t)m * 256 + col]       = v0;
            *(float2*)&outp[(size_t)(m + 8) * 256 + col] = v1;
        }
    }
}

// ---------------------------------------------------------------------------
// K2: per-(b,h) stats with 2x2 thread tiling of the 32x32 kv outer product
// grid (B*H, 32); block 256; each block does 256 rows
// ---------------------------------------------------------------------------
__global__ __launch_bounds__(256) void stats_kernel(
    const float* __restrict__ sinp, const float* __restrict__ cosp)
{
    const int bh = blockIdx.x;
    const int b  = bh >> 3;
    const int h  = bh & 7;
    const int t  = threadIdx.x;
    const int d2 = (t & 15) * 2;
    const int e2 = (t >> 4) * 2;
    const int lr = t >> 5;          // 0..7 row in group
    const int lc = t & 31;          // col

    __shared__ float ks[8][32];
    __shared__ float vs[8][32];

    const int n0 = blockIdx.y * 256;
    float a00 = 0.f, a01 = 0.f, a10 = 0.f, a11 = 0.f;
    float ksp = 0.f, vsp = 0.f;

    for (int s = 0; s < 256; s += 8) {
        const int n = n0 + s + lr;
        const size_t base = ((size_t)(b * N_ + n)) * INTERNAL_ + h * HD_;
        float kv0 = g_k[base + lc];
        float vv  = g_v[base + lc];
        float kvn = __shfl_xor_sync(0xffffffffu, kv0, 1);
        float sn = sinp[n * HD_ + lc];
        float cs = cosp[n * HD_ + lc];
        float shifted = (lc & 1) ? (kv0 * cs + kvn * sn) : (kv0 * cs - kvn * sn);
        __syncthreads();
        ks[lr][lc] = shifted;
        vs[lr][lc] = vv;
        ksp += kv0;
        vsp += vv;
        __syncthreads();
#pragma unroll
        for (int r = 0; r < 8; r++) {
            float2 kk = *(float2*)&ks[r][d2];
            float2 ve = *(float2*)&vs[r][e2];
            a00 += kk.x * ve.x; a01 += kk.x * ve.y;
            a10 += kk.y * ve.x; a11 += kk.y * ve.y;
        }
    }

    const float s2 = SCALE_ / (float)N_;
    atomicAdd(&g_kv[bh * 1024 + (d2    ) * 32 + e2    ], a00 * s2);
    atomicAdd(&g_kv[bh * 1024 + (d2    ) * 32 + e2 + 1], a01 * s2);
    atomicAdd(&g_kv[bh * 1024 + (d2 + 1) * 32 + e2    ], a10 * s2);
    atomicAdd(&g_kv[bh * 1024 + (d2 + 1) * 32 + e2 + 1], a11 * s2);
    atomicAdd(&g_ksum[bh * 32 + lc], ksp);
    atomicAdd(&g_vsum[bh * 32 + lc], vsp);
}

// ---------------------------------------------------------------------------
// K3: per-token combine; warp = head, 8 tokens per warp, kv state in regs
// grid BNTOT/8, block 256
// ---------------------------------------------------------------------------
__global__ __launch_bounds__(256) void token_kernel(
    const float* __restrict__ sinp, const float* __restrict__ cosp,
    const float* __restrict__ Wl,   const float* __restrict__ bl)
{
    const int lane = threadIdx.x & 31;
    const int h    = threadIdx.x >> 5;
    const int tok0 = blockIdx.x * 8;
    const int b    = tok0 >> 13;
    const int bh   = b * H_ + h;
    const int c    = h * HD_ + lane;

    const float invN = 1.0f / (float)N_;

    float kvr[32];
#pragma unroll
    for (int d = 0; d < 32; d++)
        kvr[d] = g_kv[bh * 1024 + d * 32 + lane];
    const float km = g_ksum[bh * 32 + lane] * invN;
    const float vm = g_vsum[bh * 32 + lane] * invN;
    const float w0 = Wl[c * 3 + 0], w1 = Wl[c * 3 + 1], w2 = Wl[c * 3 + 2];
    const float blc = bl[c];

#pragma unroll
    for (int i = 0; i < 8; i++) {
        const int tok = tok0 + i;
        const int n = tok & (N_ - 1);
        const size_t base = (size_t)tok * INTERNAL_;

        float q = g_q[base + c];

        float zp = q * km;
#pragma unroll
        for (int o = 16; o; o >>= 1) zp += __shfl_xor_sync(0xffffffffu, zp, o);
        float z = zp * SCALE_;

        float qn = __shfl_xor_sync(0xffffffffu, q, 1);
        float sn = sinp[n * HD_ + lane];
        float cs = cosp[n * HD_ + lane];
        float qs = (lane & 1) ? (q * cs + qn * sn) : (q * cs - qn * sn);

        float attn = 0.f;
#pragma unroll
        for (int d = 0; d < 32; d++)
            attn += __shfl_sync(0xffffffffu, qs, d) * kvr[d];

        float res = attn * (1.0f + 1.0f / (z + 1e-6f)) - z * vm;

        float vprev = (n > 0)      ? g_v[base - 256 + c] : 0.f;
        float vcur  = g_v[base + c];
        float vnext = (n < N_ - 1) ? g_v[base + 256 + c] : 0.f;
        float lepe = vprev * w0 + vcur * w1 + vnext * w2 + blc;

        float tv = (res + lepe) * g_o[base + c];
        __nv_bfloat16 hv = __float2bfloat16(tv);
        g_th[base + c] = hv;
        g_tl[base + c] = __float2bfloat16(tv - __bfloat162float(hv));
    }
}

// ---------------------------------------------------------------------------
// Launch
// ---------------------------------------------------------------------------
extern "C" void kernel_launch(void* const* d_in, const int* in_sizes, int n_in,
                              void* d_out, int out_size)
{
    const float* x      = (const float*)d_in[0];
    const float* sinp   = (const float*)d_in[1];
    const float* cosp   = (const float*)d_in[2];
    const float* W_qkvo = (const float*)d_in[3];
    const float* b_qkvo = (const float*)d_in[4];
    const float* W_lepe = (const float*)d_in[5];
    const float* b_lepe = (const float*)d_in[6];
    const float* W_proj = (const float*)d_in[7];
    const float* b_proj = (const float*)d_in[8];
    float* out = (float*)d_out;

    __nv_bfloat16 *xh, *xl, *wqh, *wql, *wph, *wpl, *th, *tl;
    cudaGetSymbolAddress((void**)&xh,  g_xh);
    cudaGetSymbolAddress((void**)&xl,  g_xl);
    cudaGetSymbolAddress((void**)&wqh, g_wqh);
    cudaGetSymbolAddress((void**)&wql, g_wql);
    cudaGetSymbolAddress((void**)&wph, g_wph);
    cudaGetSymbolAddress((void**)&wpl, g_wpl);
    cudaGetSymbolAddress((void**)&th,  g_th);
    cudaGetSymbolAddress((void**)&tl,  g_tl);

    const int SMEM_BYTES = 2 * STG_U32 * 4;  // 80KB
    cudaFuncSetAttribute(mma_gemm<1>, cudaFuncAttributeMaxDynamicSharedMemorySize, SMEM_BYTES);
    cudaFuncSetAttribute(mma_gemm<0>, cudaFuncAttributeMaxDynamicSharedMemorySize, SMEM_BYTES);

    zero_stats_kernel<<<(B_*H_*HD_*HD_ + 255) / 256, 256>>>();

    {
        int n1 = BNTOT * DIM_;
        split_kernel<<<(n1/4 + 255)/256, 256>>>(x, xh, xl, n1);
        int n2 = 4 * INTERNAL_ * DIM_;
        split_kernel<<<(n2/4 + 255)/256, 256>>>(W_qkvo, wqh, wql, n2);
        int n3 = DIM_ * INTERNAL_;
        split_kernel<<<(n3/4 + 255)/256, 256>>>(W_proj, wph, wpl, n3);
    }

    mma_gemm<1><<<dim3(8, 256), 256, SMEM_BYTES>>>(xh, xl, wqh, wql, b_qkvo, nullptr);

    stats_kernel<<<dim3(B_ * H_, 32), 256>>>(sinp, cosp);

    token_kernel<<<BNTOT / 8, 256>>>(sinp, cosp, W_lepe, b_lepe);

    mma_gemm<0><<<dim3(2, 256), 256, SMEM_BYTES>>>(th, tl, wph, wpl, b_proj, out);
}